// round 15
// baseline (speedup 1.0000x reference)
#include <cuda_runtime.h>
#include <cuda_bf16.h>
#include <cstdint>

// ---------------------------------------------------------------------------
// Problem constants (B=1)
// ---------------------------------------------------------------------------
static constexpr int C_   = 256;
static constexpr int HW_  = 4096;     // 64*64
static constexpr int S_   = 32768;    // 8*64*64
static constexpr int SA_  = 20480;    // 5*64*64 active (last 5 frames)
static constexpr int S0_  = S_ - SA_; // 12288
static constexpr float INV_TEMP = 10.0f;

// ---------------------------------------------------------------------------
// Device scratch
// ---------------------------------------------------------------------------
__device__ __align__(16) __nv_bfloat16 g_Ks_hi [SA_ * C_];   // [j][o]  (k-softmaxed)
__device__ __align__(16) __nv_bfloat16 g_Ks_lo [SA_ * C_];
__device__ __align__(16) __nv_bfloat16 g_Qs_hi [C_ * HW_];   // [o][hw] (q-softmaxed)
__device__ __align__(16) __nv_bfloat16 g_Qs_lo [C_ * HW_];
__device__ __align__(16) __nv_bfloat16 g_Wq_hi[C_ * C_], g_Wq_lo[C_ * C_];
__device__ __align__(16) __nv_bfloat16 g_Wk_hi[C_ * C_], g_Wk_lo[C_ * C_];
__device__ __align__(16) __nv_bfloat16 g_Wv_hi[C_ * C_], g_Wv_lo[C_ * C_];
__device__ __align__(16) float g_Qlog[C_ * HW_];   // q logits (split-K accumulator)
__device__ __align__(16) float g_T2  [C_ * C_];    // split-K accumulator [a][o]
__device__ __align__(16) float g_G   [C_ * C_];    // split-K accumulator [c][o]

// ---------------------------------------------------------------------------
// PTX helpers (compute_100-safe)
// ---------------------------------------------------------------------------
__device__ __forceinline__ uint32_t smem_u32(const void* p) {
    uint32_t a;
    asm("{ .reg .u64 t; cvta.to.shared.u64 t, %1; cvt.u32.u64 %0, t; }" : "=r"(a) : "l"(p));
    return a;
}
__device__ __forceinline__ void cp16(uint32_t dst, const void* src) {
    asm volatile("cp.async.cg.shared.global [%0], [%1], 16;" :: "r"(dst), "l"(src));
}
__device__ __forceinline__ void cp_commit() {
    asm volatile("cp.async.commit_group;" ::: "memory");
}
template<int N>
__device__ __forceinline__ void cp_wait() {
    asm volatile("cp.async.wait_group %0;" :: "n"(N) : "memory");
}
__device__ __forceinline__ void ldm_x4(uint32_t* r, uint32_t addr) {
    asm volatile("ldmatrix.sync.aligned.m8n8.x4.shared.b16 {%0,%1,%2,%3}, [%4];"
                 : "=r"(r[0]), "=r"(r[1]), "=r"(r[2]), "=r"(r[3]) : "r"(addr));
}
__device__ __forceinline__ void ldm_x4_t(uint32_t* r, uint32_t addr) {
    asm volatile("ldmatrix.sync.aligned.m8n8.x4.trans.shared.b16 {%0,%1,%2,%3}, [%4];"
                 : "=r"(r[0]), "=r"(r[1]), "=r"(r[2]), "=r"(r[3]) : "r"(addr));
}
__device__ __forceinline__ void mma16816(float* c, const uint32_t* a, const uint32_t* b) {
    asm volatile(
        "mma.sync.aligned.m16n8k16.row.col.f32.bf16.bf16.f32 "
        "{%0,%1,%2,%3}, {%4,%5,%6,%7}, {%8,%9}, {%0,%1,%2,%3};"
        : "+f"(c[0]), "+f"(c[1]), "+f"(c[2]), "+f"(c[3])
        : "r"(a[0]), "r"(a[1]), "r"(a[2]), "r"(a[3]), "r"(b[0]), "r"(b[1]));
}
__device__ __forceinline__ void split_bf16(float v, __nv_bfloat16& h, __nv_bfloat16& l) {
    h = __float2bfloat16(v);
    l = __float2bfloat16(v - __bfloat162float(h));
}
__device__ __forceinline__ uint32_t pack2(__nv_bfloat16 a, __nv_bfloat16 b) {
    return (uint32_t)__bfloat16_as_ushort(a) | ((uint32_t)__bfloat16_as_ushort(b) << 16);
}
__device__ __forceinline__ void split4(float4 v, uint2& ph, uint2& pl) {
    __nv_bfloat16 h0, l0, h1, l1, h2, l2, h3, l3;
    split_bf16(v.x, h0, l0); split_bf16(v.y, h1, l1);
    split_bf16(v.z, h2, l2); split_bf16(v.w, h3, l3);
    ph = make_uint2(pack2(h0, h1), pack2(h2, h3));
    pl = make_uint2(pack2(l0, l1), pack2(l2, l3));
}

// ---------------------------------------------------------------------------
// 3 weight matrices (256x256) fp32 -> bf16 hi/lo, one launch via grid.z
// ---------------------------------------------------------------------------
__global__ void convW3_kernel(const float* __restrict__ s0, const float* __restrict__ s1,
                              const float* __restrict__ s2,
                              __nv_bfloat16* __restrict__ h0, __nv_bfloat16* __restrict__ l0,
                              __nv_bfloat16* __restrict__ h1, __nv_bfloat16* __restrict__ l1,
                              __nv_bfloat16* __restrict__ h2, __nv_bfloat16* __restrict__ l2)
{
    const float* src = (blockIdx.z == 0) ? s0 : (blockIdx.z == 1) ? s1 : s2;
    __nv_bfloat16* hi = (blockIdx.z == 0) ? h0 : (blockIdx.z == 1) ? h1 : h2;
    __nv_bfloat16* lo = (blockIdx.z == 0) ? l0 : (blockIdx.z == 1) ? l1 : l2;
    int idx = blockIdx.x * blockDim.x + threadIdx.x;
    float4 v = *reinterpret_cast<const float4*>(src + idx * 4);
    uint2 ph, pl;
    split4(v, ph, pl);
    *reinterpret_cast<uint2*>(hi + idx * 4) = ph;
    *reinterpret_cast<uint2*>(lo + idx * 4) = pl;
}

// ---------------------------------------------------------------------------
// Generic tensor-core GEMM (R9-proven):  D[m,n] += sum_k A[m,k]*B[n,k].
// BM=BN=128, BK=32, 256 threads, 2-stage. Epilogue: fp32 atomicAdd.
// ---------------------------------------------------------------------------
static constexpr int ABUF = 10240;   // 128 x 80
static constexpr int BBUF = 8704;    // 32 x 272
static constexpr int OFF_B = 4 * ABUF;             // 40960
static constexpr int GEMM_SMEM = OFF_B + 4 * BBUF; // 75776

template<bool AF32, bool BF32>
__global__ void __launch_bounds__(256, 2) gemm_uni_kernel(
    const __nv_bfloat16* __restrict__ Ah, const __nv_bfloat16* __restrict__ Al,
    const float* __restrict__ Af, int aLd,
    const __nv_bfloat16* __restrict__ Bh, const __nv_bfloat16* __restrict__ Bl,
    const float* __restrict__ Bf, int bLd,
    float* __restrict__ out, int outLd, int kPerCta)
{
    extern __shared__ char smem[];
    uint32_t sb = smem_u32(smem);
    const int tid  = threadIdx.x;
    const int wid  = tid >> 5;
    const int lane = tid & 31;
    const int m0 = blockIdx.y * 128;
    const int n0 = blockIdx.x * 128;
    const int kStart = blockIdx.z * kPerCta;
    const int nChunks = kPerCta >> 5;

    const int wm = wid >> 2, wn = wid & 3;
    const int mBase = wm * 64, nBase = wn * 32;
    const int g = lane >> 2, t = lane & 3;
    const int mat = lane >> 3, r = lane & 7;

    const uint32_t aFrag = (uint32_t)(mBase + (mat & 1) * 8 + r) * 80 + (mat >> 1) * 16;
    const uint32_t bFrag = (uint32_t)((mat & 1) * 8 + r) * 272 + (nBase + (mat >> 1) * 8) * 2;

    float acc[4][4][4];
#pragma unroll
    for (int i = 0; i < 4; i++)
#pragma unroll
        for (int j = 0; j < 4; j++)
#pragma unroll
            for (int e = 0; e < 4; e++) acc[i][j][e] = 0.0f;

    float4 afb[4], bfb[4];

    auto ldg_f32 = [&](int kOff) {
        if (AF32) {
#pragma unroll
            for (int i = 0; i < 4; i++) {
                int slot = tid + i * 256;
                afb[i] = *reinterpret_cast<const float4*>(
                    Af + (size_t)(m0 + (slot >> 3)) * aLd + kOff + (slot & 7) * 4);
            }
        }
        if (BF32) {
#pragma unroll
            for (int i = 0; i < 4; i++) {
                int slot = tid + i * 256;
                bfb[i] = *reinterpret_cast<const float4*>(
                    Bf + (size_t)(kOff + (slot >> 5)) * bLd + n0 + (slot & 31) * 4);
            }
        }
    };
    auto sts_f32 = [&](int st) {
        if (AF32) {
#pragma unroll
            for (int i = 0; i < 4; i++) {
                int slot = tid + i * 256;
                int row = slot >> 3, c4 = (slot & 7) * 4;
                uint2 ph, pl;
                split4(afb[i], ph, pl);
                *reinterpret_cast<uint2*>(smem + (st * 2 + 0) * ABUF + row * 80 + c4 * 2) = ph;
                *reinterpret_cast<uint2*>(smem + (st * 2 + 1) * ABUF + row * 80 + c4 * 2) = pl;
            }
        }
        if (BF32) {
#pragma unroll
            for (int i = 0; i < 4; i++) {
                int slot = tid + i * 256;
                int row = slot >> 5, c4 = (slot & 31) * 4;
                uint2 ph, pl;
                split4(bfb[i], ph, pl);
                *reinterpret_cast<uint2*>(smem + OFF_B + (st * 2 + 0) * BBUF + row * 272 + c4 * 2) = ph;
                *reinterpret_cast<uint2*>(smem + OFF_B + (st * 2 + 1) * BBUF + row * 272 + c4 * 2) = pl;
            }
        }
    };
    auto cpa = [&](int st, int kOff) {
        if (!AF32) {
#pragma unroll
            for (int i = 0; i < 4; i++) {
                int idx = tid + i * 256;
                int hl = idx >> 9, rem = idx & 511;
                int row = rem >> 2, ch = rem & 3;
                cp16(sb + (st * 2 + hl) * ABUF + row * 80 + ch * 16,
                     (hl ? Al : Ah) + (size_t)(m0 + row) * aLd + kOff + ch * 8);
            }
        }
        if (!BF32) {
#pragma unroll
            for (int i = 0; i < 4; i++) {
                int idx = tid + i * 256;
                int hl = idx >> 9, rem = idx & 511;
                int row = rem >> 4, ch = rem & 15;
                cp16(sb + OFF_B + (st * 2 + hl) * BBUF + row * 272 + ch * 16,
                     (hl ? Bl : Bh) + (size_t)(kOff + row) * bLd + n0 + ch * 8);
            }
        }
    };

    cpa(0, kStart);
    cp_commit();
    ldg_f32(kStart);
    if (nChunks > 1) { cpa(1, kStart + 32); cp_commit(); }

    for (int ch = 0; ch < nChunks; ch++) {
        const int st = ch & 1;
        sts_f32(st);
        if (ch + 1 < nChunks) cp_wait<1>(); else cp_wait<0>();
        __syncthreads();
        if (ch + 1 < nChunks) ldg_f32(kStart + (ch + 1) * 32);

        const uint32_t aHiB = sb + (st * 2 + 0) * ABUF;
        const uint32_t aLoB = sb + (st * 2 + 1) * ABUF;
        const uint32_t bHiB = sb + OFF_B + (st * 2 + 0) * BBUF;
        const uint32_t bLoB = sb + OFF_B + (st * 2 + 1) * BBUF;
#pragma unroll
        for (int kk = 0; kk < 2; kk++) {
            uint32_t bh[8], bl[8];
#pragma unroll
            for (int p = 0; p < 2; p++) {
                ldm_x4_t(&bh[p * 4], bHiB + bFrag + kk * 4352 + p * 32);
                ldm_x4_t(&bl[p * 4], bLoB + bFrag + kk * 4352 + p * 32);
            }
#pragma unroll
            for (int mt = 0; mt < 4; mt++) {
                uint32_t ah[4], al[4];
                ldm_x4(ah, aHiB + aFrag + mt * 1280 + kk * 32);
                ldm_x4(al, aLoB + aFrag + mt * 1280 + kk * 32);
#pragma unroll
                for (int nt = 0; nt < 4; nt++)
                    mma16816(acc[mt][nt], ah, &bh[(nt >> 1) * 4 + (nt & 1) * 2]);
#pragma unroll
                for (int nt = 0; nt < 4; nt++)
                    mma16816(acc[mt][nt], ah, &bl[(nt >> 1) * 4 + (nt & 1) * 2]);
#pragma unroll
                for (int nt = 0; nt < 4; nt++)
                    mma16816(acc[mt][nt], al, &bh[(nt >> 1) * 4 + (nt & 1) * 2]);
            }
        }
        __syncthreads();
        if (ch + 2 < nChunks) { cpa(st, kStart + (ch + 2) * 32); cp_commit(); }
    }

#pragma unroll
    for (int mt = 0; mt < 4; mt++) {
#pragma unroll
        for (int nt = 0; nt < 4; nt++) {
            int row = m0 + mBase + mt * 16 + g;
            int col = n0 + nBase + nt * 8 + 2 * t;
            float* p0 = out + (size_t)row * outLd + col;
            float* p1 = out + (size_t)(row + 8) * outLd + col;
            atomicAdd(p0,     acc[mt][nt][0]);
            atomicAdd(p0 + 1, acc[mt][nt][1]);
            atomicAdd(p1,     acc[mt][nt][2]);
            atomicAdd(p1 + 1, acc[mt][nt][3]);
        }
    }
}

// ---------------------------------------------------------------------------
// GEMM1 fused (BM=80 for 2 CTAs/SM, single wave): Klog[j][o] = key^T . Wk^T,
// k-softmax over o, store Ks [j][o] bf16 hi/lo. (verified correct in R14)
// ---------------------------------------------------------------------------
static constexpr int KS_BBUF  = 20480;                 // 256 x 80
static constexpr int KS_OFF_A = 4 * KS_BBUF;           // 81920
static constexpr int KS_ABUF  = 5632;                  // 32 x 176
static constexpr int KS_SMEM  = KS_OFF_A + 2 * KS_ABUF;  // 93184

__global__ void __launch_bounds__(256, 2) gemm_ksm80_kernel(
    const float* __restrict__ keyP,          // key + S0_, ld = S_
    const __nv_bfloat16* __restrict__ Bh, const __nv_bfloat16* __restrict__ Bl,
    __nv_bfloat16* __restrict__ Ks_hi, __nv_bfloat16* __restrict__ Ks_lo)
{
    extern __shared__ char smem[];
    uint32_t sb = smem_u32(smem);
    const int tid  = threadIdx.x;
    const int wid  = tid >> 5;
    const int lane = tid & 31;
    const int j0 = blockIdx.x * 80;

    const int nBase = wid * 32;
    const int g = lane >> 2, t = lane & 3;
    const int mat = lane >> 3, r = lane & 7;

    const uint32_t aFragT = (uint32_t)((mat >> 1) * 8 + r) * 176 + (mat & 1) * 16;
    const uint32_t bFrag = (uint32_t)(nBase + (mat >> 1) * 8 + r) * 80 + (mat & 1) * 16;

    float acc[5][4][4];
#pragma unroll
    for (int i = 0; i < 5; i++)
#pragma unroll
        for (int j = 0; j < 4; j++)
#pragma unroll
            for (int e = 0; e < 4; e++) acc[i][j][e] = 0.0f;

    float4 afb[3];
    auto ldg_a = [&](int kOff) {
#pragma unroll
        for (int i = 0; i < 3; i++) {
            int slot = tid + i * 256;
            if (slot < 640) {
                int row = slot / 20, c4 = (slot % 20) * 4;
                afb[i] = *reinterpret_cast<const float4*>(
                    keyP + (size_t)(kOff + row) * S_ + j0 + c4);
            }
        }
    };
    auto sts_a = [&]() {
#pragma unroll
        for (int i = 0; i < 3; i++) {
            int slot = tid + i * 256;
            if (slot < 640) {
                int row = slot / 20, c4 = (slot % 20) * 4;
                uint2 ph, pl;
                split4(afb[i], ph, pl);
                *reinterpret_cast<uint2*>(smem + KS_OFF_A + row * 176 + c4 * 2) = ph;
                *reinterpret_cast<uint2*>(smem + KS_OFF_A + KS_ABUF + row * 176 + c4 * 2) = pl;
            }
        }
    };
    auto cpb = [&](int st, int kOff) {
#pragma unroll
        for (int i = 0; i < 8; i++) {
            int idx = tid + i * 256;
            int hl = idx >> 10, rem = idx & 1023;
            int row = rem >> 2, ch = rem & 3;
            cp16(sb + (st * 2 + hl) * KS_BBUF + row * 80 + ch * 16,
                 (hl ? Bl : Bh) + (size_t)row * C_ + kOff + ch * 8);
        }
    };

    cpb(0, 0);
    cp_commit();
    ldg_a(0);
    cpb(1, 32);
    cp_commit();

    const int nChunks = 8;
    for (int ch = 0; ch < nChunks; ch++) {
        const int st = ch & 1;
        sts_a();
        if (ch + 1 < nChunks) cp_wait<1>(); else cp_wait<0>();
        __syncthreads();
        if (ch + 1 < nChunks) ldg_a((ch + 1) * 32);

        const uint32_t aHiB = sb + KS_OFF_A;
        const uint32_t aLoB = sb + KS_OFF_A + KS_ABUF;
        const uint32_t bHiB = sb + (st * 2 + 0) * KS_BBUF;
        const uint32_t bLoB = sb + (st * 2 + 1) * KS_BBUF;
#pragma unroll
        for (int kk = 0; kk < 2; kk++) {
            uint32_t bh8[8], bl8[8];
#pragma unroll
            for (int p = 0; p < 2; p++) {
                ldm_x4(&bh8[p * 4], bHiB + bFrag + p * 1280 + kk * 32);
                ldm_x4(&bl8[p * 4], bLoB + bFrag + p * 1280 + kk * 32);
            }
#pragma unroll
            for (int mt = 0; mt < 5; mt++) {
                uint32_t ah[4], al[4];
                ldm_x4_t(ah, aHiB + aFragT + mt * 32 + kk * 2816);
                ldm_x4_t(al, aLoB + aFragT + mt * 32 + kk * 2816);
#pragma unroll
                for (int nt = 0; nt < 4; nt++)
                    mma16816(acc[mt][nt], ah, &bh8[(nt >> 1) * 4 + (nt & 1) * 2]);
#pragma unroll
                for (int nt = 0; nt < 4; nt++)
                    mma16816(acc[mt][nt], ah, &bl8[(nt >> 1) * 4 + (nt & 1) * 2]);
#pragma unroll
                for (int nt = 0; nt < 4; nt++)
                    mma16816(acc[mt][nt], al, &bh8[(nt >> 1) * 4 + (nt & 1) * 2]);
            }
        }
        __syncthreads();
        if (ch + 2 < nChunks) { cpb(st, (ch + 2) * 32); cp_commit(); }
    }

    // fused epilogue: row softmax over 256 cols
    float* redA = reinterpret_cast<float*>(smem);       // 80 rows x 8 warps
    float* redB = redA + 640;

    float rmax[5][2];
#pragma unroll
    for (int mt = 0; mt < 5; mt++) {
#pragma unroll
        for (int h = 0; h < 2; h++) {
            float m = -1e30f;
#pragma unroll
            for (int nt = 0; nt < 4; nt++) {
                m = fmaxf(m, acc[mt][nt][h * 2 + 0]);
                m = fmaxf(m, acc[mt][nt][h * 2 + 1]);
            }
            m = fmaxf(m, __shfl_xor_sync(0xffffffffu, m, 1));
            m = fmaxf(m, __shfl_xor_sync(0xffffffffu, m, 2));
            if (t == 0) redA[(mt * 16 + h * 8 + g) * 8 + wid] = m;
        }
    }
    __syncthreads();
#pragma unroll
    for (int mt = 0; mt < 5; mt++)
#pragma unroll
        for (int h = 0; h < 2; h++) {
            int row = mt * 16 + h * 8 + g;
            float m = -1e30f;
#pragma unroll
            for (int w = 0; w < 8; w++) m = fmaxf(m, redA[row * 8 + w]);
            rmax[mt][h] = m * INV_TEMP;
        }

    float rinv[5][2];
#pragma unroll
    for (int mt = 0; mt < 5; mt++) {
#pragma unroll
        for (int h = 0; h < 2; h++) {
            float s = 0.0f;
#pragma unroll
            for (int nt = 0; nt < 4; nt++) {
#pragma unroll
                for (int e2 = 0; e2 < 2; e2++) {
                    float w = __expf(acc[mt][nt][h * 2 + e2] * INV_TEMP - rmax[mt][h]);
                    acc[mt][nt][h * 2 + e2] = w;
                    s += w;
                }
            }
            s += __shfl_xor_sync(0xffffffffu, s, 1);
            s += __shfl_xor_sync(0xffffffffu, s, 2);
            if (t == 0) redB[(mt * 16 + h * 8 + g) * 8 + wid] = s;
        }
    }
    __syncthreads();
#pragma unroll
    for (int mt = 0; mt < 5; mt++)
#pragma unroll
        for (int h = 0; h < 2; h++) {
            int row = mt * 16 + h * 8 + g;
            float s = 0.0f;
#pragma unroll
            for (int w = 0; w < 8; w++) s += redB[row * 8 + w];
            rinv[mt][h] = 1.0f / s;
        }

#pragma unroll
    for (int mt = 0; mt < 5; mt++) {
#pragma unroll
        for (int h = 0; h < 2; h++) {
            int j = j0 + mt * 16 + h * 8 + g;
#pragma unroll
            for (int nt = 0; nt < 4; nt++) {
                int col = nBase + nt * 8 + 2 * t;
                float w0 = acc[mt][nt][h * 2 + 0] * rinv[mt][h];
                float w1 = acc[mt][nt][h * 2 + 1] * rinv[mt][h];
                __nv_bfloat16 h0, l0, h1, l1;
                split_bf16(w0, h0, l0);
                split_bf16(w1, h1, l1);
                size_t o = (size_t)j * C_ + col;
                *reinterpret_cast<uint32_t*>(Ks_hi + o) = pack2(h0, h1);
                *reinterpret_cast<uint32_t*>(Ks_lo + o) = pack2(l0, l1);
            }
        }
    }
}

// ---------------------------------------------------------------------------
// q softmax over hw (rows of 4096), 512 threads: fp32 -> bf16 hi/lo
// ---------------------------------------------------------------------------
__global__ void __launch_bounds__(512) qsoftmax_kernel(
    const float* __restrict__ Qlog,
    __nv_bfloat16* __restrict__ Qs_hi, __nv_bfloat16* __restrict__ Qs_lo)
{
    constexpr int NT = 512, NE = 8;
    const float* row = Qlog + (size_t)blockIdx.x * HW_;
    __shared__ float sred[32];
    const int tid = threadIdx.x;
    const int lane = tid & 31;
    const int wid = tid >> 5;

    float v[NE];
    float m = -1e30f;
#pragma unroll
    for (int e = 0; e < NE; e++) {
        v[e] = row[tid + e * NT] * INV_TEMP;
        m = fmaxf(m, v[e]);
    }
#pragma unroll
    for (int o = 16; o > 0; o >>= 1) m = fmaxf(m, __shfl_xor_sync(0xffffffffu, m, o));
    if (lane == 0) sred[wid] = m;
    __syncthreads();
    if (wid == 0) {
        float tv = (lane < 16) ? sred[lane] : -1e30f;
#pragma unroll
        for (int o = 16; o > 0; o >>= 1) tv = fmaxf(tv, __shfl_xor_sync(0xffffffffu, tv, o));
        if (lane == 0) sred[0] = tv;
    }
    __syncthreads();
    m = sred[0];
    __syncthreads();

    float sum = 0.0f;
#pragma unroll
    for (int e = 0; e < NE; e++) {
        v[e] = __expf(v[e] - m);
        sum += v[e];
    }
#pragma unroll
    for (int o = 16; o > 0; o >>= 1) sum += __shfl_xor_sync(0xffffffffu, sum, o);
    if (lane == 0) sred[wid] = sum;
    __syncthreads();
    if (wid == 0) {
        float tv = (lane < 16) ? sred[lane] : 0.0f;
#pragma unroll
        for (int o = 16; o > 0; o >>= 1) tv += __shfl_xor_sync(0xffffffffu, tv, o);
        if (lane == 0) sred[0] = tv;
    }
    __syncthreads();
    float inv = 1.0f / sred[0];
    size_t base = (size_t)blockIdx.x * HW_;
#pragma unroll
    for (int e = 0; e < NE; e++) {
        float w = v[e] * inv;
        __nv_bfloat16 h, l;
        split_bf16(w, h, l);
        Qs_hi[base + tid + e * NT] = h;
        Qs_lo[base + tid + e * NT] = l;
    }
}

// Zero T2 + G + out in one launch
__global__ void zero3_kernel(float* __restrict__ a, int na,
                             float* __restrict__ b, int nb,
                             float* __restrict__ c, int nc)
{
    int i = blockIdx.x * blockDim.x + threadIdx.x;
    if (i < na) a[i] = 0.0f;
    else if (i < na + nb) b[i - na] = 0.0f;
    else if (i < na + nb + nc) c[i - na - nb] = 0.0f;
}

__global__ void zero_kernel(float* __restrict__ p, int n)
{
    int i = blockIdx.x * blockDim.x + threadIdx.x;
    if (i < n) p[i] = 0.0f;
}

// ---------------------------------------------------------------------------
// Launch (R9 schedule; only ksm swapped for the 80-row single-wave version)
// ---------------------------------------------------------------------------
extern "C" void kernel_launch(void* const* d_in, const int* in_sizes, int n_in,
                              void* d_out, int out_size)
{
    (void)in_sizes; (void)n_in; (void)out_size;
    const float* query = (const float*)d_in[0]; // (C, HW)
    const float* key   = (const float*)d_in[1]; // (C, S)
    const float* value = (const float*)d_in[2]; // (C, S)
    const float* Wq    = (const float*)d_in[3]; // (C, C)
    const float* Wk    = (const float*)d_in[4];
    const float* Wv    = (const float*)d_in[5];
    float* out = (float*)d_out;                 // (C, HW)

    static bool s_init = false;
    static cudaStream_t s1, s2;
    static cudaEvent_t evF, evJ1, evJ2;
    if (!s_init) {
        cudaStreamCreateWithFlags(&s1, cudaStreamNonBlocking);
        cudaStreamCreateWithFlags(&s2, cudaStreamNonBlocking);
        cudaEventCreateWithFlags(&evF,  cudaEventDisableTiming);
        cudaEventCreateWithFlags(&evJ1, cudaEventDisableTiming);
        cudaEventCreateWithFlags(&evJ2, cudaEventDisableTiming);
        cudaFuncSetAttribute(gemm_uni_kernel<false, true>, cudaFuncAttributeMaxDynamicSharedMemorySize, GEMM_SMEM);
        cudaFuncSetAttribute(gemm_uni_kernel<true, false>, cudaFuncAttributeMaxDynamicSharedMemorySize, GEMM_SMEM);
        cudaFuncSetAttribute(gemm_ksm80_kernel, cudaFuncAttributeMaxDynamicSharedMemorySize, KS_SMEM);
        s_init = true;
    }

    __nv_bfloat16 *Ks_hi, *Ks_lo, *Qs_hi, *Qs_lo;
    __nv_bfloat16 *Wq_hi, *Wq_lo, *Wk_hi, *Wk_lo, *Wv_hi, *Wv_lo;
    float *Qlog, *T2, *G;
    cudaGetSymbolAddress((void**)&Ks_hi, g_Ks_hi);
    cudaGetSymbolAddress((void**)&Ks_lo, g_Ks_lo);
    cudaGetSymbolAddress((void**)&Qs_hi, g_Qs_hi);
    cudaGetSymbolAddress((void**)&Qs_lo, g_Qs_lo);
    cudaGetSymbolAddress((void**)&Wq_hi, g_Wq_hi);
    cudaGetSymbolAddress((void**)&Wq_lo, g_Wq_lo);
    cudaGetSymbolAddress((void**)&Wk_hi, g_Wk_hi);
    cudaGetSymbolAddress((void**)&Wk_lo, g_Wk_lo);
    cudaGetSymbolAddress((void**)&Wv_hi, g_Wv_hi);
    cudaGetSymbolAddress((void**)&Wv_lo, g_Wv_lo);
    cudaGetSymbolAddress((void**)&Qlog,  g_Qlog);
    cudaGetSymbolAddress((void**)&T2,    g_T2);
    cudaGetSymbolAddress((void**)&G,     g_G);

    // main: weight conversion, then fork
    convW3_kernel<<<dim3(64, 1, 3), 256>>>(Wq, Wk, Wv, Wq_hi, Wq_lo, Wk_hi, Wk_lo, Wv_hi, Wv_lo);
    cudaEventRecord(evF, 0);
    cudaStreamWaitEvent(s1, evF, 0);
    cudaStreamWaitEvent(s2, evF, 0);

    // s1: Ks path (ksm80: 256 CTAs, 2 CTAs/SM, single wave)
    gemm_ksm80_kernel<<<SA_ / 80, 256, KS_SMEM, s1>>>(
        key + S0_, Wk_hi, Wk_lo, Ks_hi, Ks_lo);
    cudaEventRecord(evJ1, s1);

    // s2: Qs path (split-K 2)
    zero_kernel<<<(C_ * HW_ + 255) / 256, 256, 0, s2>>>(Qlog, C_ * HW_);
    gemm_uni_kernel<false, true><<<dim3(HW_ / 128, C_ / 128, 2), 256, GEMM_SMEM, s2>>>(
        Wq_hi, Wq_lo, nullptr, C_, nullptr, nullptr, query, HW_, Qlog, HW_, C_ / 2);
    qsoftmax_kernel<<<C_, 512, 0, s2>>>(Qlog, Qs_hi, Qs_lo);
    cudaEventRecord(evJ2, s2);

    // main: zero T2 + G + out in one launch (overlaps both branches)
    {
        int total = C_ * C_ * 2 + C_ * HW_;
        zero3_kernel<<<(total + 255) / 256, 256>>>(T2, C_ * C_, G, C_ * C_, out, C_ * HW_);
    }

    // join Ks path -> GEMM3 (T2, split-K 32), GEMM4 (G, split-K 8)
    cudaStreamWaitEvent(0, evJ1, 0);
    gemm_uni_kernel<true, false><<<dim3(C_ / 128, C_ / 128, 32), 256, GEMM_SMEM>>>(
        nullptr, nullptr, value + S0_, S_, Ks_hi, Ks_lo, nullptr, C_, T2, C_, SA_ / 32);
    gemm_uni_kernel<false, true><<<dim3(C_ / 128, C_ / 128, 8), 256, GEMM_SMEM>>>(
        Wv_hi, Wv_lo, nullptr, C_, nullptr, nullptr, T2, C_, G, C_, C_ / 8);

    // join Qs path -> GEMM5 (split-K 2)
    cudaStreamWaitEvent(0, evJ2, 0);
    gemm_uni_kernel<true, false><<<dim3(HW_ / 128, C_ / 128, 2), 256, GEMM_SMEM>>>(
        nullptr, nullptr, G, C_, Qs_hi, Qs_lo, nullptr, HW_, out, HW_, C_ / 2);
}

// round 16
// speedup vs baseline: 1.0882x; 1.0882x over previous
#include <cuda_runtime.h>
#include <cuda_bf16.h>
#include <cstdint>

// ---------------------------------------------------------------------------
// Problem constants (B=1)
// ---------------------------------------------------------------------------
static constexpr int C_   = 256;
static constexpr int HW_  = 4096;     // 64*64
static constexpr int S_   = 32768;    // 8*64*64
static constexpr int SA_  = 20480;    // 5*64*64 active (last 5 frames)
static constexpr int S0_  = S_ - SA_; // 12288
static constexpr float INV_TEMP = 10.0f;

// ---------------------------------------------------------------------------
// Device scratch
// ---------------------------------------------------------------------------
__device__ __align__(16) __nv_bfloat16 g_Ks_hi [SA_ * C_];   // [j][o]  (k-softmaxed)
__device__ __align__(16) __nv_bfloat16 g_Ks_lo [SA_ * C_];
__device__ __align__(16) __nv_bfloat16 g_Qs_hi [C_ * HW_];   // [o][hw] (q-softmaxed)
__device__ __align__(16) __nv_bfloat16 g_Qs_lo [C_ * HW_];
__device__ __align__(16) __nv_bfloat16 g_Wq_hi[C_ * C_], g_Wq_lo[C_ * C_];
__device__ __align__(16) __nv_bfloat16 g_Wk_hi[C_ * C_], g_Wk_lo[C_ * C_];
__device__ __align__(16) __nv_bfloat16 g_Wv_hi[C_ * C_], g_Wv_lo[C_ * C_];
__device__ __align__(16) float g_Qlog[C_ * HW_];   // q logits (split-K accumulator)
__device__ __align__(16) float g_T2  [C_ * C_];    // split-K accumulator [a][o]
__device__ __align__(16) float g_G   [C_ * C_];    // split-K accumulator [c][o]

// ---------------------------------------------------------------------------
// PTX helpers (compute_100-safe)
// ---------------------------------------------------------------------------
__device__ __forceinline__ uint32_t smem_u32(const void* p) {
    uint32_t a;
    asm("{ .reg .u64 t; cvta.to.shared.u64 t, %1; cvt.u32.u64 %0, t; }" : "=r"(a) : "l"(p));
    return a;
}
__device__ __forceinline__ void cp16(uint32_t dst, const void* src) {
    asm volatile("cp.async.cg.shared.global [%0], [%1], 16;" :: "r"(dst), "l"(src));
}
__device__ __forceinline__ void cp_commit() {
    asm volatile("cp.async.commit_group;" ::: "memory");
}
template<int N>
__device__ __forceinline__ void cp_wait() {
    asm volatile("cp.async.wait_group %0;" :: "n"(N) : "memory");
}
__device__ __forceinline__ void ldm_x4(uint32_t* r, uint32_t addr) {
    asm volatile("ldmatrix.sync.aligned.m8n8.x4.shared.b16 {%0,%1,%2,%3}, [%4];"
                 : "=r"(r[0]), "=r"(r[1]), "=r"(r[2]), "=r"(r[3]) : "r"(addr));
}
__device__ __forceinline__ void ldm_x4_t(uint32_t* r, uint32_t addr) {
    asm volatile("ldmatrix.sync.aligned.m8n8.x4.trans.shared.b16 {%0,%1,%2,%3}, [%4];"
                 : "=r"(r[0]), "=r"(r[1]), "=r"(r[2]), "=r"(r[3]) : "r"(addr));
}
__device__ __forceinline__ void mma16816(float* c, const uint32_t* a, const uint32_t* b) {
    asm volatile(
        "mma.sync.aligned.m16n8k16.row.col.f32.bf16.bf16.f32 "
        "{%0,%1,%2,%3}, {%4,%5,%6,%7}, {%8,%9}, {%0,%1,%2,%3};"
        : "+f"(c[0]), "+f"(c[1]), "+f"(c[2]), "+f"(c[3])
        : "r"(a[0]), "r"(a[1]), "r"(a[2]), "r"(a[3]), "r"(b[0]), "r"(b[1]));
}
__device__ __forceinline__ void split_bf16(float v, __nv_bfloat16& h, __nv_bfloat16& l) {
    h = __float2bfloat16(v);
    l = __float2bfloat16(v - __bfloat162float(h));
}
__device__ __forceinline__ uint32_t pack2(__nv_bfloat16 a, __nv_bfloat16 b) {
    return (uint32_t)__bfloat16_as_ushort(a) | ((uint32_t)__bfloat16_as_ushort(b) << 16);
}
__device__ __forceinline__ void split4(float4 v, uint2& ph, uint2& pl) {
    __nv_bfloat16 h0, l0, h1, l1, h2, l2, h3, l3;
    split_bf16(v.x, h0, l0); split_bf16(v.y, h1, l1);
    split_bf16(v.z, h2, l2); split_bf16(v.w, h3, l3);
    ph = make_uint2(pack2(h0, h1), pack2(h2, h3));
    pl = make_uint2(pack2(l0, l1), pack2(l2, l3));
}

// ---------------------------------------------------------------------------
// 3 weight matrices (256x256) fp32 -> bf16 hi/lo, one launch via grid.z
// ---------------------------------------------------------------------------
__global__ void convW3_kernel(const float* __restrict__ s0, const float* __restrict__ s1,
                              const float* __restrict__ s2,
                              __nv_bfloat16* __restrict__ h0, __nv_bfloat16* __restrict__ l0,
                              __nv_bfloat16* __restrict__ h1, __nv_bfloat16* __restrict__ l1,
                              __nv_bfloat16* __restrict__ h2, __nv_bfloat16* __restrict__ l2)
{
    const float* src = (blockIdx.z == 0) ? s0 : (blockIdx.z == 1) ? s1 : s2;
    __nv_bfloat16* hi = (blockIdx.z == 0) ? h0 : (blockIdx.z == 1) ? h1 : h2;
    __nv_bfloat16* lo = (blockIdx.z == 0) ? l0 : (blockIdx.z == 1) ? l1 : l2;
    int idx = blockIdx.x * blockDim.x + threadIdx.x;
    float4 v = *reinterpret_cast<const float4*>(src + idx * 4);
    uint2 ph, pl;
    split4(v, ph, pl);
    *reinterpret_cast<uint2*>(hi + idx * 4) = ph;
    *reinterpret_cast<uint2*>(lo + idx * 4) = pl;
}

// ---------------------------------------------------------------------------
// Generic tensor-core GEMM:  D[m,n] += sum_k A[m,k]*B[n,k], bf16x3 split.
// A: normal layout: bf16 pair (!AF32) or fp32 (AF32, LDG->reg->split->STS).
// B: TRANS source [k][n]: bf16 pair (!BF32) or fp32 (BF32).
// BM=BN=128, BK=32, 256 threads, 2-stage. Epilogue: fp32 atomicAdd.
// MMA issue order: term-outer (hh,hl,lh) x nt-inner -> acc reuse distance 4.
// ---------------------------------------------------------------------------
static constexpr int ABUF = 10240;   // 128 x 80
static constexpr int BBUF = 8704;    // 32 x 272
static constexpr int OFF_B = 4 * ABUF;             // 40960
static constexpr int GEMM_SMEM = OFF_B + 4 * BBUF; // 75776

template<bool AF32, bool BF32>
__global__ void __launch_bounds__(256, 2) gemm_uni_kernel(
    const __nv_bfloat16* __restrict__ Ah, const __nv_bfloat16* __restrict__ Al,
    const float* __restrict__ Af, int aLd,
    const __nv_bfloat16* __restrict__ Bh, const __nv_bfloat16* __restrict__ Bl,
    const float* __restrict__ Bf, int bLd,
    float* __restrict__ out, int outLd, int kPerCta)
{
    extern __shared__ char smem[];
    uint32_t sb = smem_u32(smem);
    const int tid  = threadIdx.x;
    const int wid  = tid >> 5;
    const int lane = tid & 31;
    const int m0 = blockIdx.y * 128;
    const int n0 = blockIdx.x * 128;
    const int kStart = blockIdx.z * kPerCta;
    const int nChunks = kPerCta >> 5;

    const int wm = wid >> 2, wn = wid & 3;
    const int mBase = wm * 64, nBase = wn * 32;
    const int g = lane >> 2, t = lane & 3;
    const int mat = lane >> 3, r = lane & 7;

    const uint32_t aFrag = (uint32_t)(mBase + (mat & 1) * 8 + r) * 80 + (mat >> 1) * 16;
    const uint32_t bFrag = (uint32_t)((mat & 1) * 8 + r) * 272 + (nBase + (mat >> 1) * 8) * 2;

    float acc[4][4][4];
#pragma unroll
    for (int i = 0; i < 4; i++)
#pragma unroll
        for (int j = 0; j < 4; j++)
#pragma unroll
            for (int e = 0; e < 4; e++) acc[i][j][e] = 0.0f;

    float4 afb[4], bfb[4];

    auto ldg_f32 = [&](int kOff) {
        if (AF32) {
#pragma unroll
            for (int i = 0; i < 4; i++) {
                int slot = tid + i * 256;
                afb[i] = *reinterpret_cast<const float4*>(
                    Af + (size_t)(m0 + (slot >> 3)) * aLd + kOff + (slot & 7) * 4);
            }
        }
        if (BF32) {
#pragma unroll
            for (int i = 0; i < 4; i++) {
                int slot = tid + i * 256;
                bfb[i] = *reinterpret_cast<const float4*>(
                    Bf + (size_t)(kOff + (slot >> 5)) * bLd + n0 + (slot & 31) * 4);
            }
        }
    };
    auto sts_f32 = [&](int st) {
        if (AF32) {
#pragma unroll
            for (int i = 0; i < 4; i++) {
                int slot = tid + i * 256;
                int row = slot >> 3, c4 = (slot & 7) * 4;
                uint2 ph, pl;
                split4(afb[i], ph, pl);
                *reinterpret_cast<uint2*>(smem + (st * 2 + 0) * ABUF + row * 80 + c4 * 2) = ph;
                *reinterpret_cast<uint2*>(smem + (st * 2 + 1) * ABUF + row * 80 + c4 * 2) = pl;
            }
        }
        if (BF32) {
#pragma unroll
            for (int i = 0; i < 4; i++) {
                int slot = tid + i * 256;
                int row = slot >> 5, c4 = (slot & 31) * 4;
                uint2 ph, pl;
                split4(bfb[i], ph, pl);
                *reinterpret_cast<uint2*>(smem + OFF_B + (st * 2 + 0) * BBUF + row * 272 + c4 * 2) = ph;
                *reinterpret_cast<uint2*>(smem + OFF_B + (st * 2 + 1) * BBUF + row * 272 + c4 * 2) = pl;
            }
        }
    };
    auto cpa = [&](int st, int kOff) {
        if (!AF32) {
#pragma unroll
            for (int i = 0; i < 4; i++) {
                int idx = tid + i * 256;
                int hl = idx >> 9, rem = idx & 511;
                int row = rem >> 2, ch = rem & 3;
                cp16(sb + (st * 2 + hl) * ABUF + row * 80 + ch * 16,
                     (hl ? Al : Ah) + (size_t)(m0 + row) * aLd + kOff + ch * 8);
            }
        }
        if (!BF32) {
#pragma unroll
            for (int i = 0; i < 4; i++) {
                int idx = tid + i * 256;
                int hl = idx >> 9, rem = idx & 511;
                int row = rem >> 4, ch = rem & 15;
                cp16(sb + OFF_B + (st * 2 + hl) * BBUF + row * 272 + ch * 16,
                     (hl ? Bl : Bh) + (size_t)(kOff + row) * bLd + n0 + ch * 8);
            }
        }
    };

    cpa(0, kStart);
    cp_commit();
    ldg_f32(kStart);
    if (nChunks > 1) { cpa(1, kStart + 32); cp_commit(); }

    for (int ch = 0; ch < nChunks; ch++) {
        const int st = ch & 1;
        sts_f32(st);
        if (ch + 1 < nChunks) cp_wait<1>(); else cp_wait<0>();
        __syncthreads();
        if (ch + 1 < nChunks) ldg_f32(kStart + (ch + 1) * 32);

        const uint32_t aHiB = sb + (st * 2 + 0) * ABUF;
        const uint32_t aLoB = sb + (st * 2 + 1) * ABUF;
        const uint32_t bHiB = sb + OFF_B + (st * 2 + 0) * BBUF;
        const uint32_t bLoB = sb + OFF_B + (st * 2 + 1) * BBUF;
#pragma unroll
        for (int kk = 0; kk < 2; kk++) {
            uint32_t bh[8], bl[8];
#pragma unroll
            for (int p = 0; p < 2; p++) {
                ldm_x4_t(&bh[p * 4], bHiB + bFrag + kk * 4352 + p * 32);
                ldm_x4_t(&bl[p * 4], bLoB + bFrag + kk * 4352 + p * 32);
            }
#pragma unroll
            for (int mt = 0; mt < 4; mt++) {
                uint32_t ah[4], al[4];
                ldm_x4(ah, aHiB + aFrag + mt * 1280 + kk * 32);
                ldm_x4(al, aLoB + aFrag + mt * 1280 + kk * 32);
#pragma unroll
                for (int nt = 0; nt < 4; nt++)
                    mma16816(acc[mt][nt], ah, &bh[(nt >> 1) * 4 + (nt & 1) * 2]);
#pragma unroll
                for (int nt = 0; nt < 4; nt++)
                    mma16816(acc[mt][nt], ah, &bl[(nt >> 1) * 4 + (nt & 1) * 2]);
#pragma unroll
                for (int nt = 0; nt < 4; nt++)
                    mma16816(acc[mt][nt], al, &bh[(nt >> 1) * 4 + (nt & 1) * 2]);
            }
        }
        __syncthreads();
        if (ch + 2 < nChunks) { cpa(st, kStart + (ch + 2) * 32); cp_commit(); }
    }

#pragma unroll
    for (int mt = 0; mt < 4; mt++) {
#pragma unroll
        for (int nt = 0; nt < 4; nt++) {
            int row = m0 + mBase + mt * 16 + g;
            int col = n0 + nBase + nt * 8 + 2 * t;
            float* p0 = out + (size_t)row * outLd + col;
            float* p1 = out + (size_t)(row + 8) * outLd + col;
            atomicAdd(p0,     acc[mt][nt][0]);
            atomicAdd(p0 + 1, acc[mt][nt][1]);
            atomicAdd(p1,     acc[mt][nt][2]);
            atomicAdd(p1 + 1, acc[mt][nt][3]);
        }
    }
}

// ---------------------------------------------------------------------------
// GEMM1 fused: Klog[j][o] = sum_c key[c][j]*Wk[o][c], then k-softmax over o,
// store Ks [j][o] bf16 hi/lo row-major. A fp32 trans via reg-convert.
// ---------------------------------------------------------------------------
static constexpr int KSM_BBUF  = 20480;                 // 256 x 80
static constexpr int KSM_OFF_A = 4 * KSM_BBUF;          // 81920
static constexpr int KSM_ABUF  = 8704;                  // 32 x 272
static constexpr int KSM_SMEM  = KSM_OFF_A + 4 * KSM_ABUF;   // 116736

__global__ void __launch_bounds__(256, 1) gemm_ksm_kernel(
    const float* __restrict__ keyP,          // key + S0_, ld = S_
    const __nv_bfloat16* __restrict__ Bh, const __nv_bfloat16* __restrict__ Bl,
    __nv_bfloat16* __restrict__ Ks_hi, __nv_bfloat16* __restrict__ Ks_lo)
{
    extern __shared__ char smem[];
    uint32_t sb = smem_u32(smem);
    const int tid  = threadIdx.x;
    const int wid  = tid >> 5;
    const int lane = tid & 31;
    const int j0 = blockIdx.x * 128;

    const int wm = wid >> 2, wn = wid & 3;
    const int mBase = wm * 64, nBase = wn * 64;
    const int g = lane >> 2, t = lane & 3;
    const int mat = lane >> 3, r = lane & 7;

    const uint32_t aFragT = (uint32_t)((mat >> 1) * 8 + r) * 272 + (mBase + (mat & 1) * 8) * 2;
    const uint32_t bFrag = (uint32_t)(nBase + (mat >> 1) * 8 + r) * 80 + (mat & 1) * 16;

    float acc[4][8][4];
#pragma unroll
    for (int i = 0; i < 4; i++)
#pragma unroll
        for (int j = 0; j < 8; j++)
#pragma unroll
            for (int e = 0; e < 4; e++) acc[i][j][e] = 0.0f;

    float4 afb[4];
    auto ldg_a = [&](int kOff) {
#pragma unroll
        for (int i = 0; i < 4; i++) {
            int slot = tid + i * 256;
            afb[i] = *reinterpret_cast<const float4*>(
                keyP + (size_t)(kOff + (slot >> 5)) * S_ + j0 + (slot & 31) * 4);
        }
    };
    auto sts_a = [&](int st) {
#pragma unroll
        for (int i = 0; i < 4; i++) {
            int slot = tid + i * 256;
            int row = slot >> 5, c4 = (slot & 31) * 4;
            uint2 ph, pl;
            split4(afb[i], ph, pl);
            *reinterpret_cast<uint2*>(smem + KSM_OFF_A + (st * 2 + 0) * KSM_ABUF + row * 272 + c4 * 2) = ph;
            *reinterpret_cast<uint2*>(smem + KSM_OFF_A + (st * 2 + 1) * KSM_ABUF + row * 272 + c4 * 2) = pl;
        }
    };
    auto cpb = [&](int st, int kOff) {
#pragma unroll
        for (int i = 0; i < 8; i++) {
            int idx = tid + i * 256;
            int hl = idx >> 10, rem = idx & 1023;
            int row = rem >> 2, ch = rem & 3;
            cp16(sb + (st * 2 + hl) * KSM_BBUF + row * 80 + ch * 16,
                 (hl ? Bl : Bh) + (size_t)row * C_ + kOff + ch * 8);
        }
    };

    cpb(0, 0);
    cp_commit();
    ldg_a(0);
    cpb(1, 32);
    cp_commit();

    const int nChunks = 8;
    for (int ch = 0; ch < nChunks; ch++) {
        const int st = ch & 1;
        sts_a(st);
        if (ch + 1 < nChunks) cp_wait<1>(); else cp_wait<0>();
        __syncthreads();
        if (ch + 1 < nChunks) ldg_a((ch + 1) * 32);

        const uint32_t aHiB = sb + KSM_OFF_A + (st * 2 + 0) * KSM_ABUF;
        const uint32_t aLoB = sb + KSM_OFF_A + (st * 2 + 1) * KSM_ABUF;
        const uint32_t bHiB = sb + (st * 2 + 0) * KSM_BBUF;
        const uint32_t bLoB = sb + (st * 2 + 1) * KSM_BBUF;
#pragma unroll
        for (int kk = 0; kk < 2; kk++) {
            uint32_t ah[4][4], al[4][4];
#pragma unroll
            for (int mt = 0; mt < 4; mt++) {
                ldm_x4_t(ah[mt], aHiB + aFragT + kk * 4352 + mt * 32);
                ldm_x4_t(al[mt], aLoB + aFragT + kk * 4352 + mt * 32);
            }
#pragma unroll
            for (int ph = 0; ph < 2; ph++) {
                uint32_t bh8[8], bl8[8];
#pragma unroll
                for (int pl = 0; pl < 2; pl++) {
                    ldm_x4(&bh8[pl * 4], bHiB + bFrag + (ph * 2 + pl) * 1280 + kk * 32);
                    ldm_x4(&bl8[pl * 4], bLoB + bFrag + (ph * 2 + pl) * 1280 + kk * 32);
                }
#pragma unroll
                for (int mt = 0; mt < 4; mt++) {
#pragma unroll
                    for (int l = 0; l < 4; l++)
                        mma16816(acc[mt][ph * 4 + l], ah[mt], &bh8[(l >> 1) * 4 + (l & 1) * 2]);
#pragma unroll
                    for (int l = 0; l < 4; l++)
                        mma16816(acc[mt][ph * 4 + l], ah[mt], &bl8[(l >> 1) * 4 + (l & 1) * 2]);
#pragma unroll
                    for (int l = 0; l < 4; l++)
                        mma16816(acc[mt][ph * 4 + l], al[mt], &bh8[(l >> 1) * 4 + (l & 1) * 2]);
                }
            }
        }
        __syncthreads();
        if (ch + 2 < nChunks) { cpb(st, (ch + 2) * 32); cp_commit(); }
    }

    // fused epilogue: row softmax over 256 cols
    float* redA = reinterpret_cast<float*>(smem);
    float* redB = redA + 512;

    float rmax[4][2];
#pragma unroll
    for (int mt = 0; mt < 4; mt++) {
#pragma unroll
        for (int h = 0; h < 2; h++) {
            float m = -1e30f;
#pragma unroll
            for (int nt = 0; nt < 8; nt++) {
                m = fmaxf(m, acc[mt][nt][h * 2 + 0]);
                m = fmaxf(m, acc[mt][nt][h * 2 + 1]);
            }
            m = fmaxf(m, __shfl_xor_sync(0xffffffffu, m, 1));
            m = fmaxf(m, __shfl_xor_sync(0xffffffffu, m, 2));
            if (t == 0) redA[(mBase + mt * 16 + h * 8 + g) * 4 + wn] = m;
        }
    }
    __syncthreads();
#pragma unroll
    for (int mt = 0; mt < 4; mt++)
#pragma unroll
        for (int h = 0; h < 2; h++) {
            int row = mBase + mt * 16 + h * 8 + g;
            float m = fmaxf(fmaxf(redA[row * 4], redA[row * 4 + 1]),
                            fmaxf(redA[row * 4 + 2], redA[row * 4 + 3]));
            rmax[mt][h] = m * INV_TEMP;
        }

    float rinv[4][2];
#pragma unroll
    for (int mt = 0; mt < 4; mt++) {
#pragma unroll
        for (int h = 0; h < 2; h++) {
            float s = 0.0f;
#pragma unroll
            for (int nt = 0; nt < 8; nt++) {
#pragma unroll
                for (int e2 = 0; e2 < 2; e2++) {
                    float w = __expf(acc[mt][nt][h * 2 + e2] * INV_TEMP - rmax[mt][h]);
                    acc[mt][nt][h * 2 + e2] = w;
                    s += w;
                }
            }
            s += __shfl_xor_sync(0xffffffffu, s, 1);
            s += __shfl_xor_sync(0xffffffffu, s, 2);
            if (t == 0) redB[(mBase + mt * 16 + h * 8 + g) * 4 + wn] = s;
        }
    }
    __syncthreads();
#pragma unroll
    for (int mt = 0; mt < 4; mt++)
#pragma unroll
        for (int h = 0; h < 2; h++) {
            int row = mBase + mt * 16 + h * 8 + g;
            float s = redB[row * 4] + redB[row * 4 + 1] + redB[row * 4 + 2] + redB[row * 4 + 3];
            rinv[mt][h] = 1.0f / s;
        }

#pragma unroll
    for (int mt = 0; mt < 4; mt++) {
#pragma unroll
        for (int h = 0; h < 2; h++) {
            int j = j0 + mBase + mt * 16 + h * 8 + g;
#pragma unroll
            for (int nt = 0; nt < 8; nt++) {
                int col = nBase + nt * 8 + 2 * t;
                float w0 = acc[mt][nt][h * 2 + 0] * rinv[mt][h];
                float w1 = acc[mt][nt][h * 2 + 1] * rinv[mt][h];
                __nv_bfloat16 h0, l0, h1, l1;
                split_bf16(w0, h0, l0);
                split_bf16(w1, h1, l1);
                size_t o = (size_t)j * C_ + col;
                *reinterpret_cast<uint32_t*>(Ks_hi + o) = pack2(h0, h1);
                *reinterpret_cast<uint32_t*>(Ks_lo + o) = pack2(l0, l1);
            }
        }
    }
}

// ---------------------------------------------------------------------------
// q softmax over hw (rows of 4096), 512 threads: fp32 -> bf16 hi/lo
// ---------------------------------------------------------------------------
__global__ void __launch_bounds__(512) qsoftmax_kernel(
    const float* __restrict__ Qlog,
    __nv_bfloat16* __restrict__ Qs_hi, __nv_bfloat16* __restrict__ Qs_lo)
{
    constexpr int NT = 512, NE = 8;
    const float* row = Qlog + (size_t)blockIdx.x * HW_;
    __shared__ float sred[32];
    const int tid = threadIdx.x;
    const int lane = tid & 31;
    const int wid = tid >> 5;

    float v[NE];
    float m = -1e30f;
#pragma unroll
    for (int e = 0; e < NE; e++) {
        v[e] = row[tid + e * NT] * INV_TEMP;
        m = fmaxf(m, v[e]);
    }
#pragma unroll
    for (int o = 16; o > 0; o >>= 1) m = fmaxf(m, __shfl_xor_sync(0xffffffffu, m, o));
    if (lane == 0) sred[wid] = m;
    __syncthreads();
    if (wid == 0) {
        float tv = (lane < 16) ? sred[lane] : -1e30f;
#pragma unroll
        for (int o = 16; o > 0; o >>= 1) tv = fmaxf(tv, __shfl_xor_sync(0xffffffffu, tv, o));
        if (lane == 0) sred[0] = tv;
    }
    __syncthreads();
    m = sred[0];
    __syncthreads();

    float sum = 0.0f;
#pragma unroll
    for (int e = 0; e < NE; e++) {
        v[e] = __expf(v[e] - m);
        sum += v[e];
    }
#pragma unroll
    for (int o = 16; o > 0; o >>= 1) sum += __shfl_xor_sync(0xffffffffu, sum, o);
    if (lane == 0) sred[wid] = sum;
    __syncthreads();
    if (wid == 0) {
        float tv = (lane < 16) ? sred[lane] : 0.0f;
#pragma unroll
        for (int o = 16; o > 0; o >>= 1) tv += __shfl_xor_sync(0xffffffffu, tv, o);
        if (lane == 0) sred[0] = tv;
    }
    __syncthreads();
    float inv = 1.0f / sred[0];
    size_t base = (size_t)blockIdx.x * HW_;
#pragma unroll
    for (int e = 0; e < NE; e++) {
        float w = v[e] * inv;
        __nv_bfloat16 h, l;
        split_bf16(w, h, l);
        Qs_hi[base + tid + e * NT] = h;
        Qs_lo[base + tid + e * NT] = l;
    }
}

// Zero T2 + G + out in one launch
__global__ void zero3_kernel(float* __restrict__ a, int na,
                             float* __restrict__ b, int nb,
                             float* __restrict__ c, int nc)
{
    int i = blockIdx.x * blockDim.x + threadIdx.x;
    if (i < na) a[i] = 0.0f;
    else if (i < na + nb) b[i - na] = 0.0f;
    else if (i < na + nb + nc) c[i - na - nb] = 0.0f;
}

__global__ void zero_kernel(float* __restrict__ p, int n)
{
    int i = blockIdx.x * blockDim.x + threadIdx.x;
    if (i < n) p[i] = 0.0f;
}

// ---------------------------------------------------------------------------
// Launch (R9 schedule — measured best: 116.7 us)
// ---------------------------------------------------------------------------
extern "C" void kernel_launch(void* const* d_in, const int* in_sizes, int n_in,
                              void* d_out, int out_size)
{
    (void)in_sizes; (void)n_in; (void)out_size;
    const float* query = (const float*)d_in[0]; // (C, HW)
    const float* key   = (const float*)d_in[1]; // (C, S)
    const float* value = (const float*)d_in[2]; // (C, S)
    const float* Wq    = (const float*)d_in[3]; // (C, C)
    const float* Wk    = (const float*)d_in[4];
    const float* Wv    = (const float*)d_in[5];
    float* out = (float*)d_out;                 // (C, HW)

    static bool s_init = false;
    static cudaStream_t s1, s2;
    static cudaEvent_t evF, evJ1, evJ2;
    if (!s_init) {
        cudaStreamCreateWithFlags(&s1, cudaStreamNonBlocking);
        cudaStreamCreateWithFlags(&s2, cudaStreamNonBlocking);
        cudaEventCreateWithFlags(&evF,  cudaEventDisableTiming);
        cudaEventCreateWithFlags(&evJ1, cudaEventDisableTiming);
        cudaEventCreateWithFlags(&evJ2, cudaEventDisableTiming);
        cudaFuncSetAttribute(gemm_uni_kernel<false, true>, cudaFuncAttributeMaxDynamicSharedMemorySize, GEMM_SMEM);
        cudaFuncSetAttribute(gemm_uni_kernel<true, false>, cudaFuncAttributeMaxDynamicSharedMemorySize, GEMM_SMEM);
        cudaFuncSetAttribute(gemm_ksm_kernel, cudaFuncAttributeMaxDynamicSharedMemorySize, KSM_SMEM);
        s_init = true;
    }

    __nv_bfloat16 *Ks_hi, *Ks_lo, *Qs_hi, *Qs_lo;
    __nv_bfloat16 *Wq_hi, *Wq_lo, *Wk_hi, *Wk_lo, *Wv_hi, *Wv_lo;
    float *Qlog, *T2, *G;
    cudaGetSymbolAddress((void**)&Ks_hi, g_Ks_hi);
    cudaGetSymbolAddress((void**)&Ks_lo, g_Ks_lo);
    cudaGetSymbolAddress((void**)&Qs_hi, g_Qs_hi);
    cudaGetSymbolAddress((void**)&Qs_lo, g_Qs_lo);
    cudaGetSymbolAddress((void**)&Wq_hi, g_Wq_hi);
    cudaGetSymbolAddress((void**)&Wq_lo, g_Wq_lo);
    cudaGetSymbolAddress((void**)&Wk_hi, g_Wk_hi);
    cudaGetSymbolAddress((void**)&Wk_lo, g_Wk_lo);
    cudaGetSymbolAddress((void**)&Wv_hi, g_Wv_hi);
    cudaGetSymbolAddress((void**)&Wv_lo, g_Wv_lo);
    cudaGetSymbolAddress((void**)&Qlog,  g_Qlog);
    cudaGetSymbolAddress((void**)&T2,    g_T2);
    cudaGetSymbolAddress((void**)&G,     g_G);

    // main: weight conversion, then fork
    convW3_kernel<<<dim3(64, 1, 3), 256>>>(Wq, Wk, Wv, Wq_hi, Wq_lo, Wk_hi, Wk_lo, Wv_hi, Wv_lo);
    cudaEventRecord(evF, 0);
    cudaStreamWaitEvent(s1, evF, 0);
    cudaStreamWaitEvent(s2, evF, 0);

    // s1: Ks path (GEMM1 + fused k-softmax)
    gemm_ksm_kernel<<<SA_ / 128, 256, KSM_SMEM, s1>>>(key + S0_, Wk_hi, Wk_lo, Ks_hi, Ks_lo);
    cudaEventRecord(evJ1, s1);

    // s2: Qs path (split-K 2)
    zero_kernel<<<(C_ * HW_ + 255) / 256, 256, 0, s2>>>(Qlog, C_ * HW_);
    gemm_uni_kernel<false, true><<<dim3(HW_ / 128, C_ / 128, 2), 256, GEMM_SMEM, s2>>>(
        Wq_hi, Wq_lo, nullptr, C_, nullptr, nullptr, query, HW_, Qlog, HW_, C_ / 2);
    qsoftmax_kernel<<<C_, 512, 0, s2>>>(Qlog, Qs_hi, Qs_lo);
    cudaEventRecord(evJ2, s2);

    // main: zero T2 + G + out in one launch (overlaps both branches)
    {
        int total = C_ * C_ * 2 + C_ * HW_;
        zero3_kernel<<<(total + 255) / 256, 256>>>(T2, C_ * C_, G, C_ * C_, out, C_ * HW_);
    }

    // join Ks path -> GEMM3 (T2, split-K 32), GEMM4 (G, split-K 8)
    cudaStreamWaitEvent(0, evJ1, 0);
    gemm_uni_kernel<true, false><<<dim3(C_ / 128, C_ / 128, 32), 256, GEMM_SMEM>>>(
        nullptr, nullptr, value + S0_, S_, Ks_hi, Ks_lo, nullptr, C_, T2, C_, SA_ / 32);
    gemm_uni_kernel<false, true><<<dim3(C_ / 128, C_ / 128, 8), 256, GEMM_SMEM>>>(
        Wv_hi, Wv_lo, nullptr, C_, nullptr, nullptr, T2, C_, G, C_, C_ / 8);

    // join Qs path -> GEMM5 (split-K 2)
    cudaStreamWaitEvent(0, evJ2, 0);
    gemm_uni_kernel<true, false><<<dim3(HW_ / 128, C_ / 128, 2), 256, GEMM_SMEM>>>(
        nullptr, nullptr, G, C_, Qs_hi, Qs_lo, nullptr, HW_, out, HW_, C_ / 2);
}